// round 14
// baseline (speedup 1.0000x reference)
#include <cuda_runtime.h>
#include <cuda_bf16.h>
#include <cuda_fp16.h>
#include <cstdint>

// ---------------------------------------------------------------------------
// Problem constants
// ---------------------------------------------------------------------------
#define NN    8192          // B*S nodes
#define DD    768           // hidden dim
#define HH    12            // heads
#define HDIM  64            // head dim
#define EE    131072        // edges
#define DEGCAP 128          // smem softmax capacity (max degree ~40 expected)

// split-bf16 GEMM constants
#define KSPLIT 2304         // 3*DD (hi|hi|lo vs hi|lo|hi)
#define NCHUNK 36           // KSPLIT/64
#define MT     128          // M tile
#define NT     128          // N tile
#define TILE_BYTES 16384    // 128 rows * 128 bytes
#define NSTAGE 4
#define GEMM_SMEM (NSTAGE * 2 * TILE_BYTES + 128)   // 128KB + pad

// ---------------------------------------------------------------------------
// Scratch (static device globals — no allocation allowed)
// ---------------------------------------------------------------------------
__device__ float g_q[NN * DD];
__device__ float g_y[NN * DD];

__device__ __half g_kh[NN * DD];         // k (fp16, score gather operand)
__device__ __half g_vh[NN * DD];         // v (fp16, gather + blend operand)
__device__ __half g_hha[NN * DD];        // intermediate h ping
__device__ __half g_hhb[NN * DD];        // intermediate h pong

__device__ int   g_cnt[NN];              // starts 0 (BSS); reset by score kernel
__device__ int   g_rowptr[NN + 1];
__device__ int   g_csr_src[EE];          // src node per CSR slot
__device__ float g_csr_attn[EE * HH];    // normalized attn (CSR order)

// split-bf16 operand storage (pre-swizzled 16KB tile blocks)
__device__ __align__(128) __nv_bfloat16 g_ax[(size_t)NN * KSPLIT];   // x  split
__device__ __align__(128) __nv_bfloat16 g_ah[(size_t)NN * KSPLIT];   // h  split
__device__ __align__(128) __nv_bfloat16 g_wqs[(size_t)DD * KSPLIT];
__device__ __align__(128) __nv_bfloat16 g_wks[(size_t)DD * KSPLIT];
__device__ __align__(128) __nv_bfloat16 g_wvs[(size_t)DD * KSPLIT];
__device__ __align__(128) __nv_bfloat16 g_wos[(size_t)DD * KSPLIT];

// ---------------------------------------------------------------------------
// helpers
// ---------------------------------------------------------------------------
__device__ __forceinline__ uint32_t smem_u32(const void* p) {
    uint32_t a;
    asm("{ .reg .u64 t; cvta.to.shared.u64 t, %1; cvt.u32.u64 %0, t; }"
        : "=r"(a) : "l"(p));
    return a;
}

__device__ __forceinline__ void ldmx4(uint32_t* r, uint32_t addr) {
    asm volatile("ldmatrix.sync.aligned.m8n8.x4.shared.b16 {%0,%1,%2,%3}, [%4];"
        : "=r"(r[0]), "=r"(r[1]), "=r"(r[2]), "=r"(r[3]) : "r"(addr));
}

__device__ __forceinline__ void mma_bf16(float* c, const uint32_t* a,
                                         uint32_t b0, uint32_t b1) {
    asm volatile(
        "mma.sync.aligned.m16n8k16.row.col.f32.bf16.bf16.f32 "
        "{%0,%1,%2,%3}, {%4,%5,%6,%7}, {%8,%9}, {%0,%1,%2,%3};"
        : "+f"(c[0]), "+f"(c[1]), "+f"(c[2]), "+f"(c[3])
        : "r"(a[0]), "r"(a[1]), "r"(a[2]), "r"(a[3]), "r"(b0), "r"(b1));
}

__device__ __forceinline__ void cp_chunk(uint32_t bufA, uint32_t bufW,
                                         const char* ga, const char* gw,
                                         int tid) {
    #pragma unroll
    for (int j = 0; j < 4; j++) {
        const uint32_t off = (uint32_t)(tid + j * 256) * 16;
        asm volatile("cp.async.cg.shared.global [%0], [%1], 16;"
            :: "r"(bufA + off), "l"(ga + off) : "memory");
        asm volatile("cp.async.cg.shared.global [%0], [%1], 16;"
            :: "r"(bufW + off), "l"(gw + off) : "memory");
    }
    asm volatile("cp.async.commit_group;" ::: "memory");
}

// ---------------------------------------------------------------------------
// split_pack (tile-block mapping): block = (kc, mtile[, wsel]).
// Writes one 16KB SW128 tile block; all indexing via shifts/masks.
// ---------------------------------------------------------------------------
__device__ __forceinline__ void split_pack_tile_body(
    const float* __restrict__ src, __nv_bfloat16* __restrict__ dst,
    int lo_seg, int kc, int mtile)
{
    const int seg   = kc / 12;                 // 12 chunks of 64 per 768 seg
    const int kbase = kc * 64 - seg * DD;      // source col of chunk start
    const bool is_lo = (seg == lo_seg);
    char* out = reinterpret_cast<char*>(dst) +
                ((size_t)mtile * NCHUNK + kc) * (size_t)TILE_BYTES;
    const float* sbase = src + (size_t)mtile * 128 * DD + kbase;

    #pragma unroll
    for (int ii = 0; ii < 4; ii++) {
        const int i  = threadIdx.x + ii * 256;    // 0..1023
        const int r  = i >> 3;                    // row 0..127
        const int gg = i & 7;                     // 16B group in row
        const float* s = sbase + (size_t)r * DD + gg * 8;
        const float4 f0 = *reinterpret_cast<const float4*>(s);
        const float4 f1 = *reinterpret_cast<const float4*>(s + 4);
        float fv[8] = {f0.x, f0.y, f0.z, f0.w, f1.x, f1.y, f1.z, f1.w};

        __align__(16) __nv_bfloat16 vals[8];
        #pragma unroll
        for (int j = 0; j < 8; j++) {
            __nv_bfloat16 hi = __float2bfloat16(fv[j]);
            vals[j] = is_lo ? __float2bfloat16(fv[j] - __bfloat162float(hi))
                            : hi;
        }
        uint32_t off = (uint32_t)(r * 128 + gg * 16);
        uint32_t sw  = off ^ ((off >> 3) & 0x70);
        *reinterpret_cast<uint4*>(out + sw) =
            *reinterpret_cast<const uint4*>(vals);
    }
}

// activations: grid (NCHUNK, NN/128)
__global__ __launch_bounds__(256) void split_pack_act(
    const float* __restrict__ src, __nv_bfloat16* __restrict__ dst)
{
    split_pack_tile_body(src, dst, 2, blockIdx.x, blockIdx.y);
}

// all 4 weights: grid (NCHUNK, DD/128, 4)
__global__ __launch_bounds__(256) void split_pack_w4(
    const float* __restrict__ w0, const float* __restrict__ w1,
    const float* __restrict__ w2, const float* __restrict__ w3,
    __nv_bfloat16* __restrict__ d0, __nv_bfloat16* __restrict__ d1,
    __nv_bfloat16* __restrict__ d2, __nv_bfloat16* __restrict__ d3)
{
    const float* src; __nv_bfloat16* dst;
    switch (blockIdx.z) {
        case 0:  src = w0; dst = d0; break;
        case 1:  src = w1; dst = d1; break;
        case 2:  src = w2; dst = d2; break;
        default: src = w3; dst = d3; break;
    }
    split_pack_tile_body(src, dst, 1, blockIdx.x, blockIdx.y);
}

// ---------------------------------------------------------------------------
// GEMM core: CTA 128x128, 8 warps (4Mx2N), K'=2304 in 36 chunks of 64,
// 4-stage cp.async pipeline, ldmatrix + m16n8k16 with REGISTER DOUBLE
// BUFFERING of fragments (prefetch ks+1 LDSMs before mma of ks).
// ---------------------------------------------------------------------------
__device__ __forceinline__ void gemm_core(
    const char* Asrc, const char* Wsrc, const float* __restrict__ bias,
    const float* __restrict__ resid, float* __restrict__ C,
    __half* __restrict__ Ch, float scale, int mtile, int ncol, uint32_t sbase)
{
    const int tid  = threadIdx.x;
    const int wid  = tid >> 5, lane = tid & 31;
    const int wm   = wid & 3, wn = wid >> 2;

    // precomputed fragment base addresses (offsets only vary with ks)
    const int ra  = wm * 32 + (lane & 15);           // A rows (mt adds 16)
    const int rb  = wn * 64 + (lane & 7) + ((lane >> 4) << 3);  // B rows (np adds 16)
    const int gra = (lane >> 4);                     // A k-group parity
    const int grb = ((lane >> 3) & 1);               // B k-group parity

    float acc[2][8][4];
    #pragma unroll
    for (int mt = 0; mt < 2; mt++)
        #pragma unroll
        for (int nt = 0; nt < 8; nt++)
            #pragma unroll
            for (int j = 0; j < 4; j++) acc[mt][nt][j] = 0.0f;

    #pragma unroll
    for (int s = 0; s < NSTAGE - 1; s++) {
        const uint32_t bA = sbase + (uint32_t)s * (2 * TILE_BYTES);
        cp_chunk(bA, bA + TILE_BYTES,
                 Asrc + (size_t)s * TILE_BYTES, Wsrc + (size_t)s * TILE_BYTES,
                 tid);
    }

    uint32_t afrag[2][2][4];   // [buf][mt][regs]
    uint32_t bfrag[2][4][4];   // [buf][np][regs]

    for (int i = 0; i < NCHUNK; i++) {
        if (i <= NCHUNK - 3)
            asm volatile("cp.async.wait_group 2;" ::: "memory");
        else if (i == NCHUNK - 2)
            asm volatile("cp.async.wait_group 1;" ::: "memory");
        else
            asm volatile("cp.async.wait_group 0;" ::: "memory");
        __syncthreads();

        if (i + NSTAGE - 1 < NCHUNK) {
            const int s = (i + NSTAGE - 1) & (NSTAGE - 1);
            const uint32_t bA = sbase + (uint32_t)s * (2 * TILE_BYTES);
            cp_chunk(bA, bA + TILE_BYTES,
                     Asrc + (size_t)(i + NSTAGE - 1) * TILE_BYTES,
                     Wsrc + (size_t)(i + NSTAGE - 1) * TILE_BYTES, tid);
        }

        const uint32_t bufA = sbase + (uint32_t)(i & (NSTAGE - 1)) * (2 * TILE_BYTES);
        const uint32_t bufW = bufA + TILE_BYTES;

        // load ks=0 fragments into buffer 0
        #pragma unroll
        for (int mt = 0; mt < 2; mt++) {
            const int r = ra + mt * 16;
            ldmx4(afrag[0][mt], bufA + r * 128 + ((gra ^ (r & 7)) << 4));
        }
        #pragma unroll
        for (int np = 0; np < 4; np++) {
            const int r = rb + np * 16;
            ldmx4(bfrag[0][np], bufW + r * 128 + ((grb ^ (r & 7)) << 4));
        }

        #pragma unroll
        for (int ks = 0; ks < 4; ks++) {
            const int cur = ks & 1;
            if (ks < 3) {                       // prefetch ks+1 fragments
                const int nxt = cur ^ 1;
                const int ga = (ks + 1) * 2 + gra;
                const int gb = (ks + 1) * 2 + grb;
                #pragma unroll
                for (int mt = 0; mt < 2; mt++) {
                    const int r = ra + mt * 16;
                    ldmx4(afrag[nxt][mt], bufA + r * 128 + ((ga ^ (r & 7)) << 4));
                }
                #pragma unroll
                for (int np = 0; np < 4; np++) {
                    const int r = rb + np * 16;
                    ldmx4(bfrag[nxt][np], bufW + r * 128 + ((gb ^ (r & 7)) << 4));
                }
            }
            #pragma unroll
            for (int mt = 0; mt < 2; mt++)
                #pragma unroll
                for (int nt = 0; nt < 8; nt++)
                    mma_bf16(acc[mt][nt], afrag[cur][mt],
                             bfrag[cur][nt >> 1][(nt & 1) * 2],
                             bfrag[cur][nt >> 1][(nt & 1) * 2 + 1]);
        }

        // fix gr for ks=0 of next chunk (gra/grb already include parity only)
    }

    const int row0 = mtile * MT + wm * 32;
    const int col0 = ncol * NT + wn * 64;
    #pragma unroll
    for (int mt = 0; mt < 2; mt++) {
        #pragma unroll
        for (int nt = 0; nt < 8; nt++) {
            const int r  = row0 + mt * 16 + (lane >> 2);
            const int cc = col0 + nt * 8 + (lane & 3) * 2;
            const float b0 = bias[cc], b1 = bias[cc + 1];
            float2 o0, o1;
            o0.x = (acc[mt][nt][0] + b0) * scale;
            o0.y = (acc[mt][nt][1] + b1) * scale;
            o1.x = (acc[mt][nt][2] + b0) * scale;
            o1.y = (acc[mt][nt][3] + b1) * scale;
            if (resid) {
                o0.x += resid[(size_t)r * DD + cc];
                o0.y += resid[(size_t)r * DD + cc + 1];
                o1.x += resid[(size_t)(r + 8) * DD + cc];
                o1.y += resid[(size_t)(r + 8) * DD + cc + 1];
            }
            if (C) {
                *reinterpret_cast<float2*>(C + (size_t)r * DD + cc)       = o0;
                *reinterpret_cast<float2*>(C + (size_t)(r + 8) * DD + cc) = o1;
            }
            if (Ch) {
                *reinterpret_cast<__half2*>(Ch + (size_t)r * DD + cc) =
                    __floats2half2_rn(o0.x, o0.y);
                *reinterpret_cast<__half2*>(Ch + (size_t)(r + 8) * DD + cc) =
                    __floats2half2_rn(o1.x, o1.y);
            }
        }
    }
}

// fused Q/K/V projection: grid (18, 64); blockIdx.x/6 selects the matrix
// q -> fp32 only; k -> fp16 only; v -> fp16 only
__global__ __launch_bounds__(256, 1)
void gemm_qkv(const __nv_bfloat16* __restrict__ Ab,
              const __nv_bfloat16* __restrict__ Wq,
              const __nv_bfloat16* __restrict__ Wk,
              const __nv_bfloat16* __restrict__ Wv,
              const float* __restrict__ bq, const float* __restrict__ bk,
              const float* __restrict__ bv,
              float* __restrict__ q, __half* __restrict__ kh,
              __half* __restrict__ vh)
{
    extern __shared__ char dyn_smem[];
    const uint32_t sbase = (smem_u32(dyn_smem) + 127u) & ~127u;
    const int sel  = blockIdx.x / 6;
    const int ncol = blockIdx.x % 6;
    const __nv_bfloat16* W = (sel == 0) ? Wq : (sel == 1) ? Wk : Wv;
    const float* bias      = (sel == 0) ? bq : (sel == 1) ? bk : bv;
    float*  C              = (sel == 0) ? q  : nullptr;
    __half* Ch             = (sel == 0) ? nullptr : (sel == 1) ? kh : vh;
    const float scale      = (sel == 0) ? 0.125f : 1.0f;

    gemm_core((const char*)Ab + (size_t)blockIdx.y * NCHUNK * TILE_BYTES,
              (const char*)W  + (size_t)ncol * NCHUNK * TILE_BYTES,
              bias, nullptr, C, Ch, scale, blockIdx.y, ncol, sbase);
}

// single GEMM (output projection): grid (6, 64)
__global__ __launch_bounds__(256, 1)
void gemm_one(const __nv_bfloat16* __restrict__ Ab,
              const __nv_bfloat16* __restrict__ Wb,
              const float* __restrict__ bias,
              const float* __restrict__ resid,
              float* __restrict__ C, float scale)
{
    extern __shared__ char dyn_smem[];
    const uint32_t sbase = (smem_u32(dyn_smem) + 127u) & ~127u;
    gemm_core((const char*)Ab + (size_t)blockIdx.y * NCHUNK * TILE_BYTES,
              (const char*)Wb + (size_t)blockIdx.x * NCHUNK * TILE_BYTES,
              bias, resid, C, nullptr, scale, blockIdx.y, blockIdx.x, sbase);
}

// ---------------------------------------------------------------------------
// CSR build (g_cnt == 0 at call entry; reset by score_softmax every call)
// ---------------------------------------------------------------------------
__global__ void count_kernel(const int* __restrict__ dst) {
    int e = blockIdx.x * blockDim.x + threadIdx.x;
    if (e < EE) atomicAdd(&g_cnt[dst[e]], 1);
}

__global__ __launch_bounds__(1024) void scan_kernel() {
    __shared__ int ssum[1024];
    const int t = threadIdx.x;
    const int base = t * 8;
    int local[8];
    int s = 0;
    #pragma unroll
    for (int i = 0; i < 8; i++) { local[i] = g_cnt[base + i]; s += local[i]; }
    ssum[t] = s;
    __syncthreads();
    for (int off = 1; off < 1024; off <<= 1) {
        int v = (t >= off) ? ssum[t - off] : 0;
        __syncthreads();
        ssum[t] += v;
        __syncthreads();
    }
    int pre = (t == 0) ? 0 : ssum[t - 1];
    #pragma unroll
    for (int i = 0; i < 8; i++) {
        g_rowptr[base + i] = pre;
        pre += local[i];
        g_cnt[base + i] = 0;               // reset for scatter pass
    }
    if (t == 1023) g_rowptr[NN] = pre;
}

__global__ void scatter_kernel(const int* __restrict__ src,
                               const int* __restrict__ dst) {
    int e = blockIdx.x * blockDim.x + threadIdx.x;
    if (e < EE) {
        int d = dst[e];
        int pos = g_rowptr[d] + atomicAdd(&g_cnt[d], 1);
        g_csr_src[pos] = src[e];
    }
}

// ---------------------------------------------------------------------------
// score_softmax: block per dst node. q (fp32) staged in smem; k gathered fp16;
// raw scores staged in smem; parallel per-head softmax; normalized attn
// written once to g_csr_attn. Global fallback for deg > DEGCAP.
// Also resets g_cnt[node] = 0 for the next call's count.
// ---------------------------------------------------------------------------
__global__ __launch_bounds__(256) void score_softmax(const float* __restrict__ am) {
    __shared__ float qs[DD];
    __shared__ float sc[DEGCAP * HH];
    __shared__ float red[8 * HH];
    __shared__ float mxs[HH], invs[HH];

    const int node = blockIdx.x;
    const int t    = threadIdx.x;
    const int wid  = t >> 5, lane = t & 31;

    qs[t]       = g_q[(size_t)node * DD + t];
    qs[t + 256] = g_q[(size_t)node * DD + t + 256];
    qs[t + 512] = g_q[(size_t)node * DD + t + 512];
    const bool m = (am[node] >= 0.0f);
    __syncthreads();

    const int beg = g_rowptr[node];
    const int deg = g_rowptr[node + 1] - beg;

    for (int s = wid; s < deg; s += 8) {
        const __half* kr = g_kh + (size_t)g_csr_src[beg + s] * DD;
        float myscore = 0.0f;
        #pragma unroll
        for (int h = 0; h < HH; h++) {
            const int i0 = h * HDIM + lane * 2;
            const float2 kf = __half22float2(
                *reinterpret_cast<const __half2*>(kr + i0));
            const float2 qf = *reinterpret_cast<const float2*>(qs + i0);
            float p = kf.x * qf.x + kf.y * qf.y;
            #pragma unroll
            for (int off = 16; off; off >>= 1)
                p += __shfl_xor_sync(0xFFFFFFFFu, p, off);
            if (lane == h) myscore = m ? p : -1.0e4f;
        }
        if (lane < HH) {
            if (s < DEGCAP) sc[s * HH + lane] = myscore;
            else g_csr_attn[(size_t)(beg + s) * HH + lane] = myscore;
        }
    }
    __syncthreads();

    if (deg <= DEGCAP) {
        if (t < 8 * HH) {
            const int h = t % HH, g = t / HH;
            float mx = -3.0e38f;
            for (int s = g; s < deg; s += 8) mx = fmaxf(mx, sc[s * HH + h]);
            red[g * HH + h] = mx;
        }
        __syncthreads();
        if (t < HH) {
            float mx = red[t];
            #pragma unroll
            for (int g = 1; g < 8; g++) mx = fmaxf(mx, red[g * HH + t]);
            mxs[t] = mx;
        }
        __syncthreads();
        if (t < 8 * HH) {
            const int h = t % HH, g = t / HH;
            const float mx = mxs[h];
            float sm = 0.0f;
            for (int s = g; s < deg; s += 8) {
                float p = __expf(sc[s * HH + h] - mx);
                sc[s * HH + h] = p;
                sm += p;
            }
            red[g * HH + h] = sm;
        }
        __syncthreads();
        if (t < HH) {
            float sm = 0.0f;
            #pragma unroll
            for (int g = 0; g < 8; g++) sm += red[g * HH + t];
            invs[t] = 1.0f / sm;
        }
        __syncthreads();
        for (int i = t; i < deg * HH; i += 256)
            g_csr_attn[(size_t)beg * HH + i] = sc[i] * invs[i % HH];
    } else {
        for (int i = t; i < DEGCAP * HH; i += 256)
            g_csr_attn[(size_t)beg * HH + i] = sc[i];
        __syncthreads();
        if (wid == 0 && lane < HH) {
            float mx = -3.0e38f;
            for (int s = 0; s < deg; s++)
                mx = fmaxf(mx, g_csr_attn[(size_t)(beg + s) * HH + lane]);
            float sm = 0.0f;
            for (int s = 0; s < deg; s++) {
                float p = __expf(g_csr_attn[(size_t)(beg + s) * HH + lane] - mx);
                g_csr_attn[(size_t)(beg + s) * HH + lane] = p;
                sm += p;
            }
            const float inv = 1.0f / sm;
            for (int s = 0; s < deg; s++)
                g_csr_attn[(size_t)(beg + s) * HH + lane] *= inv;
        }
    }

    if (t == 0) g_cnt[node] = 0;   // restore invariant for next call
}

// ---------------------------------------------------------------------------
// agg: hout[n] = 0.9 * sum attn*h[src] + 0.1 * v[n].
// 192 thr = 6 warps/node; warp owns 128 contiguous halves (2 heads).
// No __syncthreads, no smem: src/attn preloaded per 16-edge chunk into regs,
// broadcast via shfl. Last step (dst_split) writes bf16 split tiles.
// ---------------------------------------------------------------------------
__global__ __launch_bounds__(192) void agg_kernel(
    const __half* __restrict__ hin, __half* __restrict__ hout,
    __nv_bfloat16* __restrict__ dst_split)
{
    const int node = blockIdx.x;
    const int t    = threadIdx.x;
    const int w    = t >> 5, lane = t & 31;
    const int beg  = g_rowptr[node], end = g_rowptr[node + 1];
    const int col  = w * 128 + lane * 4;     // 4 contiguous halves, one head
    const int hsel = lane >> 4;              // 0 or 1 within warp's head pair

    float4 acc = {0.0f, 0.0f, 0.0f, 0.0f};

    for (int cs = beg; cs < end; cs += 16) {
        const int c = min(16, end - cs);
        int   src_r  = 0;
        float attn_r = 0.0f;
        if (lane < c) src_r = g_csr_src[cs + lane];
        {
            const int e = lane >> 1;
            if (e < c)
                attn_r = g_csr_attn[(size_t)(cs + e) * HH + (w * 2 + (lane & 1))];
        }
        #pragma unroll 4
        for (int j = 0; j < c; j++) {
            const int   srcj = __shfl_sync(0xFFFFFFFFu, src_r, j);
            const float wt   = __shfl_sync(0xFFFFFFFFu, attn_r, 2 * j + hsel);
            const uint2 pv = *reinterpret_cast<const uint2*>(
                hin + (size_t)srcj * DD + col);
            const float2 h0 = __half22float2(*reinterpret_cast<const __half2*>(&pv.x));
            const float2 h1 = __half22float2(*reinterpret_cast<const __half2*>(&pv.y));
            acc.x += wt * h0.x; acc.y += wt * h0.y;
            acc.z += wt * h1.x; acc.w += wt * h1.y;
        }
    }

    const uint2 vv = *reinterpret_cast<const uint2*>(
        g_vh + (size_t)node * DD + col);
    const float2 v0 = __half22float2(*reinterpret_cast<const __half2*>(&vv.x));
    const float2 v1 = __half22float2(*reinterpret_cast<const __half2*>(&vv.y));
    float4 o;
    o.x = 0.9f * acc.x + 0.1f * v0.x;
    o.y = 0.9f * acc.y + 0.1f * v0.y;
    o.z = 0.9f * acc.z + 0.1f * v1.x;
    o.w = 0.9f * acc.w + 0.1f * v1.y;

    if (dst_split) {
        float vals[4] = {o.x, o.y, o.z, o.w};
        __align__(8) __nv_bfloat16 hi[4], lo[4];
        #pragma unroll
        for (int j = 0; j < 4; j++) {
            hi[j] = __float2bfloat16(vals[j]);
            lo[j] = __float2bfloat16(vals[j] - __bfloat162float(hi[j]));
        }
        const int mtile = node >> 7, r = node & 127;
        #pragma unroll
        for (int seg = 0; seg < 3; seg++) {
            const int kp = col + seg * DD;
            const int kc = kp >> 6, cc = kp & 63;
            const size_t base = ((size_t)mtile * NCHUNK + kc) * (size_t)TILE_BYTES;
            uint32_t off = (uint32_t)(r * 128 + cc * 2);
            uint32_t sw  = off ^ ((off >> 3) & 0x70);
            *reinterpret_cast<uint2*>(reinterpret_cast<char*>(dst_split) + base + sw) =
                *reinterpret_cast<const uint2*>(seg == 2 ? lo : hi);
        }
    } else {
        __half2* op = reinterpret_cast<__half2*>(hout + (size_t)node * DD + col);
        op[0] = __floats2half2_rn(o.x, o.y);
        op[1] = __floats2half2_rn(o.z, o.w);
    }
}

// ---------------------------------------------------------------------------
// LayerNorm: block per row, 256 thr x 3 dims
// ---------------------------------------------------------------------------
__global__ __launch_bounds__(256) void ln_kernel(
    const float* __restrict__ y, const float* __restrict__ gamma,
    const float* __restrict__ beta, float* __restrict__ out)
{
    const int row = blockIdx.x;
    const int t   = threadIdx.x;
    const size_t base = (size_t)row * DD;

    const float x0 = y[base + t];
    const float x1 = y[base + t + 256];
    const float x2 = y[base + t + 512];

    __shared__ float sdata[256];
    sdata[t] = x0 + x1 + x2;
    __syncthreads();
    for (int off = 128; off > 0; off >>= 1) {
        if (t < off) sdata[t] += sdata[t + off];
        __syncthreads();
    }
    const float mu = sdata[0] * (1.0f / DD);
    __syncthreads();

    const float d0 = x0 - mu, d1 = x1 - mu, d2 = x2 - mu;
    sdata[t] = d0 * d0 + d1 * d1 + d2 * d2;
    __syncthreads();
    for (int off = 128; off > 0; off >>= 1) {
        if (t < off) sdata[t] += sdata[t + off];
        __syncthreads();
    }
    const float inv = rsqrtf(sdata[0] * (1.0f / DD) + 1e-12f);

    out[base + t]       = d0 * inv * gamma[t]       + beta[t];
    out[base + t + 256] = d1 * inv * gamma[t + 256] + beta[t + 256];
    out[base + t + 512] = d2 * inv * gamma[t + 512] + beta[t + 512];
}

// ---------------------------------------------------------------------------
// launch
// ---------------------------------------------------------------------------
static float* symF(const void* sym) {
    void* p = nullptr;
    cudaGetSymbolAddress(&p, sym);
    return (float*)p;
}
static __nv_bfloat16* symB(const void* sym) {
    void* p = nullptr;
    cudaGetSymbolAddress(&p, sym);
    return (__nv_bfloat16*)p;
}
static __half* symH(const void* sym) {
    void* p = nullptr;
    cudaGetSymbolAddress(&p, sym);
    return (__half*)p;
}

extern "C" void kernel_launch(void* const* d_in, const int* in_sizes, int n_in,
                              void* d_out, int out_size) {
    const float* x    = (const float*)d_in[0];
    const float* am   = (const float*)d_in[1];
    const int*   esrc = (const int*)d_in[2];
    const int*   edst = (const int*)d_in[3];
    const float* Wq   = (const float*)d_in[4];
    const float* bq   = (const float*)d_in[5];
    const float* Wk   = (const float*)d_in[6];
    const float* bk   = (const float*)d_in[7];
    const float* Wv   = (const float*)d_in[8];
    const float* bv   = (const float*)d_in[9];
    const float* Wo   = (const float*)d_in[10];
    const float* bo   = (const float*)d_in[11];
    const float* lng  = (const float*)d_in[12];
    const float* lnb  = (const float*)d_in[13];
    float* out = (float*)d_out;

    float* q  = symF(g_q);
    float* y  = symF(g_y);

    __half* kh  = symH(g_kh);
    __half* vh  = symH(g_vh);
    __half* hha = symH(g_hha);
    __half* hhb = symH(g_hhb);

    __nv_bfloat16* ax  = symB(g_ax);
    __nv_bfloat16* ah  = symB(g_ah);
    __nv_bfloat16* wqs = symB(g_wqs);
    __nv_bfloat16* wks = symB(g_wks);
    __nv_bfloat16* wvs = symB(g_wvs);
    __nv_bfloat16* wos = symB(g_wos);

    cudaFuncSetAttribute(gemm_qkv, cudaFuncAttributeMaxDynamicSharedMemorySize,
                         GEMM_SMEM);
    cudaFuncSetAttribute(gemm_one, cudaFuncAttributeMaxDynamicSharedMemorySize,
                         GEMM_SMEM);

    // launch order keeps the 4th launch (ncu capture slot) = gemm_qkv
    split_pack_act<<<dim3(NCHUNK, NN / 128), 256>>>(x, ax);
    split_pack_w4<<<dim3(NCHUNK, DD / 128, 4), 256>>>(Wq, Wk, Wv, Wo,
                                                      wqs, wks, wvs, wos);
    count_kernel<<<(EE + 255) / 256, 256>>>(edst);
    gemm_qkv<<<dim3(18, 64), 256, GEMM_SMEM>>>(ax, wqs, wks, wvs,
                                               bq, bk, bv, q, kh, vh);

    // finish CSR build
    scan_kernel<<<1, 1024>>>();
    scatter_kernel<<<(EE + 255) / 256, 256>>>(esrc, edst);

    // fused CSR-order scores + per-node softmax (+ g_cnt reset)
    score_softmax<<<NN, 256>>>(am);

    // 5 message-passing steps on fp16 h; last writes bf16 split tiles
    agg_kernel<<<NN, 192>>>(vh,  hha, nullptr);
    agg_kernel<<<NN, 192>>>(hha, hhb, nullptr);
    agg_kernel<<<NN, 192>>>(hhb, hha, nullptr);
    agg_kernel<<<NN, 192>>>(hha, hhb, nullptr);
    agg_kernel<<<NN, 192>>>(hhb, nullptr, ah);

    // output projection (+x residual), then LayerNorm
    gemm_one<<<dim3(6, 64), 256, GEMM_SMEM>>>(ah, wos, bo, x, y, 1.0f);
    ln_kernel<<<NN, 256>>>(y, lng, lnb, out);
}

// round 16
// speedup vs baseline: 1.0336x; 1.0336x over previous
#include <cuda_runtime.h>
#include <cuda_bf16.h>
#include <cuda_fp16.h>
#include <cstdint>

// ---------------------------------------------------------------------------
// Problem constants
// ---------------------------------------------------------------------------
#define NN    8192          // B*S nodes
#define DD    768           // hidden dim
#define HH    12            // heads
#define HDIM  64            // head dim
#define EE    131072        // edges
#define DEGCAP 128          // smem softmax capacity

// split-bf16 GEMM constants
#define KSPLIT 2304         // 3*DD (hi|hi|lo vs hi|lo|hi)
#define NCHUNK 36           // KSPLIT/64
#define MT     128          // M tile
#define TILE_BYTES 16384    // 128 rows * 128 bytes
#define NSTAGE 4
#define GEMM_SMEM  (NSTAGE * 2 * TILE_BYTES + 128)   // 128KB + pad (narrow)
#define GEMM_SMEMW (NSTAGE * 3 * TILE_BYTES + 128)   // 192KB + pad (wide)

// ---------------------------------------------------------------------------
// Scratch (static device globals — no allocation allowed)
// ---------------------------------------------------------------------------
__device__ float g_q[NN * DD];
__device__ float g_y[NN * DD];

__device__ __half g_kh[NN * DD];
__device__ __half g_vh[NN * DD];
__device__ __half g_hha[NN * DD];
__device__ __half g_hhb[NN * DD];

__device__ int   g_cnt[NN];
__device__ int   g_rowptr[NN + 1];
__device__ int   g_csr_src[EE];
__device__ float g_csr_attn[EE * HH];

__device__ __align__(128) __nv_bfloat16 g_ax[(size_t)NN * KSPLIT];
__device__ __align__(128) __nv_bfloat16 g_ah[(size_t)NN * KSPLIT];
__device__ __align__(128) __nv_bfloat16 g_wqs[(size_t)DD * KSPLIT];
__device__ __align__(128) __nv_bfloat16 g_wks[(size_t)DD * KSPLIT];
__device__ __align__(128) __nv_bfloat16 g_wvs[(size_t)DD * KSPLIT];
__device__ __align__(128) __nv_bfloat16 g_wos[(size_t)DD * KSPLIT];

// ---------------------------------------------------------------------------
// helpers
// ---------------------------------------------------------------------------
__device__ __forceinline__ uint32_t smem_u32(const void* p) {
    uint32_t a;
    asm("{ .reg .u64 t; cvta.to.shared.u64 t, %1; cvt.u32.u64 %0, t; }"
        : "=r"(a) : "l"(p));
    return a;
}

__device__ __forceinline__ void ldmx4(uint32_t* r, uint32_t addr) {
    asm volatile("ldmatrix.sync.aligned.m8n8.x4.shared.b16 {%0,%1,%2,%3}, [%4];"
        : "=r"(r[0]), "=r"(r[1]), "=r"(r[2]), "=r"(r[3]) : "r"(addr));
}

__device__ __forceinline__ void mma_bf16(float* c, const uint32_t* a,
                                         uint32_t b0, uint32_t b1) {
    asm volatile(
        "mma.sync.aligned.m16n8k16.row.col.f32.bf16.bf16.f32 "
        "{%0,%1,%2,%3}, {%4,%5,%6,%7}, {%8,%9}, {%0,%1,%2,%3};"
        : "+f"(c[0]), "+f"(c[1]), "+f"(c[2]), "+f"(c[3])
        : "r"(a[0]), "r"(a[1]), "r"(a[2]), "r"(a[3]), "r"(b0), "r"(b1));
}

// ---------------------------------------------------------------------------
// split_pack (tile-block mapping)
// ---------------------------------------------------------------------------
__device__ __forceinline__ void split_pack_tile_body(
    const float* __restrict__ src, __nv_bfloat16* __restrict__ dst,
    int lo_seg, int kc, int mtile)
{
    const int seg   = kc / 12;
    const int kbase = kc * 64 - seg * DD;
    const bool is_lo = (seg == lo_seg);
    char* out = reinterpret_cast<char*>(dst) +
                ((size_t)mtile * NCHUNK + kc) * (size_t)TILE_BYTES;
    const float* sbase = src + (size_t)mtile * 128 * DD + kbase;

    #pragma unroll
    for (int ii = 0; ii < 4; ii++) {
        const int i  = threadIdx.x + ii * 256;
        const int r  = i >> 3;
        const int gg = i & 7;
        const float* s = sbase + (size_t)r * DD + gg * 8;
        const float4 f0 = *reinterpret_cast<const float4*>(s);
        const float4 f1 = *reinterpret_cast<const float4*>(s + 4);
        float fv[8] = {f0.x, f0.y, f0.z, f0.w, f1.x, f1.y, f1.z, f1.w};

        __align__(16) __nv_bfloat16 vals[8];
        #pragma unroll
        for (int j = 0; j < 8; j++) {
            __nv_bfloat16 hi = __float2bfloat16(fv[j]);
            vals[j] = is_lo ? __float2bfloat16(fv[j] - __bfloat162float(hi))
                            : hi;
        }
        uint32_t off = (uint32_t)(r * 128 + gg * 16);
        uint32_t sw  = off ^ ((off >> 3) & 0x70);
        *reinterpret_cast<uint4*>(out + sw) =
            *reinterpret_cast<const uint4*>(vals);
    }
}

__global__ __launch_bounds__(256) void split_pack_act(
    const float* __restrict__ src, __nv_bfloat16* __restrict__ dst)
{
    split_pack_tile_body(src, dst, 2, blockIdx.x, blockIdx.y);
}

__global__ __launch_bounds__(256) void split_pack_w4(
    const float* __restrict__ w0, const float* __restrict__ w1,
    const float* __restrict__ w2, const float* __restrict__ w3,
    __nv_bfloat16* __restrict__ d0, __nv_bfloat16* __restrict__ d1,
    __nv_bfloat16* __restrict__ d2, __nv_bfloat16* __restrict__ d3)
{
    const float* src; __nv_bfloat16* dst;
    switch (blockIdx.z) {
        case 0:  src = w0; dst = d0; break;
        case 1:  src = w1; dst = d1; break;
        case 2:  src = w2; dst = d2; break;
        default: src = w3; dst = d3; break;
    }
    split_pack_tile_body(src, dst, 1, blockIdx.x, blockIdx.y);
}

// ---------------------------------------------------------------------------
// WIDE GEMM core (qkv): CTA 128x256, 8 warps 32x128 (4Mx2N), K'=2304,
// 4-stage cp.async pipeline. LDSM/mma = 10/32 (vs 6/16 narrow).
// q -> fp32; k,v -> fp16.
// ---------------------------------------------------------------------------
__global__ __launch_bounds__(256, 1)
void gemm_qkv(const __nv_bfloat16* __restrict__ Ab,
              const __nv_bfloat16* __restrict__ Wq,
              const __nv_bfloat16* __restrict__ Wk,
              const __nv_bfloat16* __restrict__ Wv,
              const float* __restrict__ bq, const float* __restrict__ bk,
              const float* __restrict__ bv,
              float* __restrict__ q, __half* __restrict__ kh,
              __half* __restrict__ vh)
{
    extern __shared__ char dyn_smem[];
    const uint32_t sbase = (smem_u32(dyn_smem) + 127u) & ~127u;

    const int sel  = blockIdx.x / 3;           // 0=q 1=k 2=v
    const int ncol = blockIdx.x % 3;           // 256-col tile
    const int mtile = blockIdx.y;
    const __nv_bfloat16* W = (sel == 0) ? Wq : (sel == 1) ? Wk : Wv;
    const float* bias      = (sel == 0) ? bq : (sel == 1) ? bk : bv;
    const float scale      = (sel == 0) ? 0.125f : 1.0f;

    const char* Asrc  = (const char*)Ab + (size_t)mtile * NCHUNK * TILE_BYTES;
    const char* Wsrc0 = (const char*)W  + (size_t)(2 * ncol)     * NCHUNK * TILE_BYTES;
    const char* Wsrc1 = (const char*)W  + (size_t)(2 * ncol + 1) * NCHUNK * TILE_BYTES;

    const int tid  = threadIdx.x;
    const int wid  = tid >> 5, lane = tid & 31;
    const int wm   = wid & 3, wn = wid >> 2;

    const int ra  = wm * 32 + (lane & 15);
    const int rbl = (lane & 7) + ((lane >> 4) << 3);   // B row low bits
    const int gra = (lane >> 4);
    const int grb = ((lane >> 3) & 1);

    float acc[2][16][4];
    #pragma unroll
    for (int mt = 0; mt < 2; mt++)
        #pragma unroll
        for (int nt = 0; nt < 16; nt++)
            #pragma unroll
            for (int j = 0; j < 4; j++) acc[mt][nt][j] = 0.0f;

    auto cp_stage = [&](int i, int s) {
        const uint32_t bA = sbase + (uint32_t)s * (3 * TILE_BYTES);
        const uint32_t bW = bA + TILE_BYTES;
        const char* ga  = Asrc  + (size_t)i * TILE_BYTES;
        const char* gw0 = Wsrc0 + (size_t)i * TILE_BYTES;
        const char* gw1 = Wsrc1 + (size_t)i * TILE_BYTES;
        #pragma unroll
        for (int j = 0; j < 4; j++) {
            const uint32_t off = (uint32_t)(tid + j * 256) * 16;
            asm volatile("cp.async.cg.shared.global [%0], [%1], 16;"
                :: "r"(bA + off), "l"(ga + off) : "memory");
            asm volatile("cp.async.cg.shared.global [%0], [%1], 16;"
                :: "r"(bW + off), "l"(gw0 + off) : "memory");
            asm volatile("cp.async.cg.shared.global [%0], [%1], 16;"
                :: "r"(bW + TILE_BYTES + off), "l"(gw1 + off) : "memory");
        }
        asm volatile("cp.async.commit_group;" ::: "memory");
    };

    #pragma unroll
    for (int s = 0; s < NSTAGE - 1; s++) cp_stage(s, s);

    for (int i = 0; i < NCHUNK; i++) {
        if (i <= NCHUNK - 3)
            asm volatile("cp.async.wait_group 2;" ::: "memory");
        else if (i == NCHUNK - 2)
            asm volatile("cp.async.wait_group 1;" ::: "memory");
        else
            asm volatile("cp.async.wait_group 0;" ::: "memory");
        __syncthreads();

        if (i + NSTAGE - 1 < NCHUNK)
            cp_stage(i + NSTAGE - 1, (i + NSTAGE - 1) & (NSTAGE - 1));

        const uint32_t bufA = sbase + (uint32_t)(i & (NSTAGE - 1)) * (3 * TILE_BYTES);
        const uint32_t bufW = bufA + TILE_BYTES + (uint32_t)wn * TILE_BYTES;

        #pragma unroll
        for (int ks = 0; ks < 4; ks++) {
            uint32_t a[2][4];
            #pragma unroll
            for (int mt = 0; mt < 2; mt++) {
                const int r = ra + mt * 16;
                const int g = ks * 2 + gra;
                ldmx4(a[mt], bufA + r * 128 + ((g ^ (r & 7)) << 4));
            }
            uint32_t b[8][4];
            #pragma unroll
            for (int np = 0; np < 8; np++) {
                const int r = np * 16 + rbl;      // row within this wn subtile
                const int g = ks * 2 + grb;
                ldmx4(b[np], bufW + r * 128 + ((g ^ (r & 7)) << 4));
            }
            #pragma unroll
            for (int mt = 0; mt < 2; mt++)
                #pragma unroll
                for (int nt = 0; nt < 16; nt++)
                    mma_bf16(acc[mt][nt], a[mt],
                             b[nt >> 1][(nt & 1) * 2],
                             b[nt >> 1][(nt & 1) * 2 + 1]);
        }
    }

    const int row0 = mtile * MT + wm * 32;
    const int col0 = ncol * 256 + wn * 128;
    #pragma unroll
    for (int mt = 0; mt < 2; mt++) {
        #pragma unroll
        for (int nt = 0; nt < 16; nt++) {
            const int r  = row0 + mt * 16 + (lane >> 2);
            const int cc = col0 + nt * 8 + (lane & 3) * 2;
            const float b0 = bias[cc], b1 = bias[cc + 1];
            float2 o0, o1;
            o0.x = (acc[mt][nt][0] + b0) * scale;
            o0.y = (acc[mt][nt][1] + b1) * scale;
            o1.x = (acc[mt][nt][2] + b0) * scale;
            o1.y = (acc[mt][nt][3] + b1) * scale;
            if (sel == 0) {
                *reinterpret_cast<float2*>(q + (size_t)r * DD + cc)       = o0;
                *reinterpret_cast<float2*>(q + (size_t)(r + 8) * DD + cc) = o1;
            } else {
                __half* Ch = (sel == 1) ? kh : vh;
                *reinterpret_cast<__half2*>(Ch + (size_t)r * DD + cc) =
                    __floats2half2_rn(o0.x, o0.y);
                *reinterpret_cast<__half2*>(Ch + (size_t)(r + 8) * DD + cc) =
                    __floats2half2_rn(o1.x, o1.y);
            }
        }
    }
}

// ---------------------------------------------------------------------------
// NARROW GEMM core (output projection): CTA 128x128 (round-13 path)
// ---------------------------------------------------------------------------
__global__ __launch_bounds__(256, 1)
void gemm_one(const __nv_bfloat16* __restrict__ Ab,
              const __nv_bfloat16* __restrict__ Wb,
              const float* __restrict__ bias,
              const float* __restrict__ resid,
              float* __restrict__ C, float scale)
{
    extern __shared__ char dyn_smem[];
    const uint32_t sbase = (smem_u32(dyn_smem) + 127u) & ~127u;
    const int mtile = blockIdx.y, ncol = blockIdx.x;

    const char* Asrc = (const char*)Ab + (size_t)mtile * NCHUNK * TILE_BYTES;
    const char* Wsrc = (const char*)Wb + (size_t)ncol  * NCHUNK * TILE_BYTES;

    const int tid  = threadIdx.x;
    const int wid  = tid >> 5, lane = tid & 31;
    const int wm   = wid & 3, wn = wid >> 2;

    float acc[2][8][4];
    #pragma unroll
    for (int mt = 0; mt < 2; mt++)
        #pragma unroll
        for (int nt = 0; nt < 8; nt++)
            #pragma unroll
            for (int j = 0; j < 4; j++) acc[mt][nt][j] = 0.0f;

    auto cp_stage = [&](int i, int s) {
        const uint32_t bA = sbase + (uint32_t)s * (2 * TILE_BYTES);
        const char* ga = Asrc + (size_t)i * TILE_BYTES;
        const char* gw = Wsrc + (size_t)i * TILE_BYTES;
        #pragma unroll
        for (int j = 0; j < 4; j++) {
            const uint32_t off = (uint32_t)(tid + j * 256) * 16;
            asm volatile("cp.async.cg.shared.global [%0], [%1], 16;"
                :: "r"(bA + off), "l"(ga + off) : "memory");
            asm volatile("cp.async.cg.shared.global [%0], [%1], 16;"
                :: "r"(bA + TILE_BYTES + off), "l"(gw + off) : "memory");
        }
        asm volatile("cp.async.commit_group;" ::: "memory");
    };

    #pragma unroll
    for (int s = 0; s < NSTAGE - 1; s++) cp_stage(s, s);

    for (int i = 0; i < NCHUNK; i++) {
        if (i <= NCHUNK - 3)
            asm volatile("cp.async.wait_group 2;" ::: "memory");
        else if (i == NCHUNK - 2)
            asm volatile("cp.async.wait_group 1;" ::: "memory");
        else
            asm volatile("cp.async.wait_group 0;" ::: "memory");
        __syncthreads();

        if (i + NSTAGE - 1 < NCHUNK)
            cp_stage(i + NSTAGE - 1, (i + NSTAGE - 1) & (NSTAGE - 1));

        const uint32_t bufA = sbase + (uint32_t)(i & (NSTAGE - 1)) * (2 * TILE_BYTES);
        const uint32_t bufW = bufA + TILE_BYTES;

        #pragma unroll
        for (int ks = 0; ks < 4; ks++) {
            uint32_t a[2][4];
            #pragma unroll
            for (int mt = 0; mt < 2; mt++) {
                const int r = wm * 32 + mt * 16 + (lane & 15);
                const int gr = ks * 2 + (lane >> 4);
                ldmx4(a[mt], bufA + r * 128 + ((gr ^ (r & 7)) << 4));
            }
            uint32_t b[4][4];
            #pragma unroll
            for (int np = 0; np < 4; np++) {
                const int r = wn * 64 + np * 16 + (lane & 7) + ((lane >> 4) << 3);
                const int gr = ks * 2 + ((lane >> 3) & 1);
                ldmx4(b[np], bufW + r * 128 + ((gr ^ (r & 7)) << 4));
            }
            #pragma unroll
            for (int mt = 0; mt < 2; mt++)
                #pragma unroll
                for (int nt = 0; nt < 8; nt++)
                    mma_bf16(acc[mt][nt], a[mt],
                             b[nt >> 1][(nt & 1) * 2],
                             b[nt >> 1][(nt & 1) * 2 + 1]);
        }
    }

    const int row0 = mtile * MT + wm * 32;
    const int col0 = ncol * 128 + wn * 64;
    #pragma unroll
    for (int mt = 0; mt < 2; mt++) {
        #pragma unroll
        for (int nt = 0; nt < 8; nt++) {
            const int r  = row0 + mt * 16 + (lane >> 2);
            const int cc = col0 + nt * 8 + (lane & 3) * 2;
            const float b0 = bias[cc], b1 = bias[cc + 1];
            float2 o0, o1;
            o0.x = (acc[mt][nt][0] + b0) * scale + resid[(size_t)r * DD + cc];
            o0.y = (acc[mt][nt][1] + b1) * scale + resid[(size_t)r * DD + cc + 1];
            o1.x = (acc[mt][nt][2] + b0) * scale + resid[(size_t)(r + 8) * DD + cc];
            o1.y = (acc[mt][nt][3] + b1) * scale + resid[(size_t)(r + 8) * DD + cc + 1];
            *reinterpret_cast<float2*>(C + (size_t)r * DD + cc)       = o0;
            *reinterpret_cast<float2*>(C + (size_t)(r + 8) * DD + cc) = o1;
        }
    }
}

// ---------------------------------------------------------------------------
// CSR build (g_cnt == 0 at call entry; reset by score_softmax every call)
// ---------------------------------------------------------------------------
__global__ void count_kernel(const int* __restrict__ dst) {
    int e = blockIdx.x * blockDim.x + threadIdx.x;
    if (e < EE) atomicAdd(&g_cnt[dst[e]], 1);
}

__global__ __launch_bounds__(1024) void scan_kernel() {
    __shared__ int ssum[1024];
    const int t = threadIdx.x;
    const int base = t * 8;
    int local[8];
    int s = 0;
    #pragma unroll
    for (int i = 0; i < 8; i++) { local[i] = g_cnt[base + i]; s += local[i]; }
    ssum[t] = s;
    __syncthreads();
    for (int off = 1; off < 1024; off <<= 1) {
        int v = (t >= off) ? ssum[t - off] : 0;
        __syncthreads();
        ssum[t] += v;
        __syncthreads();
    }
    int pre = (t == 0) ? 0 : ssum[t - 1];
    #pragma unroll
    for (int i = 0; i < 8; i++) {
        g_rowptr[base + i] = pre;
        pre += local[i];
        g_cnt[base + i] = 0;
    }
    if (t == 1023) g_rowptr[NN] = pre;
}

__global__ void scatter_kernel(const int* __restrict__ src,
                               const int* __restrict__ dst) {
    int e = blockIdx.x * blockDim.x + threadIdx.x;
    if (e < EE) {
        int d = dst[e];
        int pos = g_rowptr[d] + atomicAdd(&g_cnt[d], 1);
        g_csr_src[pos] = src[e];
    }
}

// ---------------------------------------------------------------------------
// score_softmax (unchanged)
// ---------------------------------------------------------------------------
__global__ __launch_bounds__(256) void score_softmax(const float* __restrict__ am) {
    __shared__ float qs[DD];
    __shared__ float sc[DEGCAP * HH];
    __shared__ float red[8 * HH];
    __shared__ float mxs[HH], invs[HH];

    const int node = blockIdx.x;
    const int t    = threadIdx.x;
    const int wid  = t >> 5, lane = t & 31;

    qs[t]       = g_q[(size_t)node * DD + t];
    qs[t + 256] = g_q[(size_t)node * DD + t + 256];
    qs[t + 512] = g_q[(size_t)node * DD + t + 512];
    const bool m = (am[node] >= 0.0f);
    __syncthreads();

    const int beg = g_rowptr[node];
    const int deg = g_rowptr[node + 1] - beg;

    for (int s = wid; s < deg; s += 8) {
        const __half* kr = g_kh + (size_t)g_csr_src[beg + s] * DD;
        float myscore = 0.0f;
        #pragma unroll
        for (int h = 0; h < HH; h++) {
            const int i0 = h * HDIM + lane * 2;
            const float2 kf = __half22float2(
                *reinterpret_cast<const __half2*>(kr + i0));
            const float2 qf = *reinterpret_cast<const float2*>(qs + i0);
            float p = kf.x * qf.x + kf.y * qf.y;
            #pragma unroll
            for (int off = 16; off; off >>= 1)
                p += __shfl_xor_sync(0xFFFFFFFFu, p, off);
            if (lane == h) myscore = m ? p : -1.0e4f;
        }
        if (lane < HH) {
            if (s < DEGCAP) sc[s * HH + lane] = myscore;
            else g_csr_attn[(size_t)(beg + s) * HH + lane] = myscore;
        }
    }
    __syncthreads();

    if (deg <= DEGCAP) {
        if (t < 8 * HH) {
            const int h = t % HH, g = t / HH;
            float mx = -3.0e38f;
            for (int s = g; s < deg; s += 8) mx = fmaxf(mx, sc[s * HH + h]);
            red[g * HH + h] = mx;
        }
        __syncthreads();
        if (t < HH) {
            float mx = red[t];
            #pragma unroll
            for (int g = 1; g < 8; g++) mx = fmaxf(mx, red[g * HH + t]);
            mxs[t] = mx;
        }
        __syncthreads();
        if (t < 8 * HH) {
            const int h = t % HH, g = t / HH;
            const float mx = mxs[h];
            float sm = 0.0f;
            for (int s = g; s < deg; s += 8) {
                float p = __expf(sc[s * HH + h] - mx);
                sc[s * HH + h] = p;
                sm += p;
            }
            red[g * HH + h] = sm;
        }
        __syncthreads();
        if (t < HH) {
            float sm = 0.0f;
            #pragma unroll
            for (int g = 0; g < 8; g++) sm += red[g * HH + t];
            invs[t] = 1.0f / sm;
        }
        __syncthreads();
        for (int i = t; i < deg * HH; i += 256)
            g_csr_attn[(size_t)beg * HH + i] = sc[i] * invs[i % HH];
    } else {
        for (int i = t; i < DEGCAP * HH; i += 256)
            g_csr_attn[(size_t)beg * HH + i] = sc[i];
        __syncthreads();
        if (wid == 0 && lane < HH) {
            float mx = -3.0e38f;
            for (int s = 0; s < deg; s++)
                mx = fmaxf(mx, g_csr_attn[(size_t)(beg + s) * HH + lane]);
            float sm = 0.0f;
            for (int s = 0; s < deg; s++) {
                float p = __expf(g_csr_attn[(size_t)(beg + s) * HH + lane] - mx);
                g_csr_attn[(size_t)(beg + s) * HH + lane] = p;
                sm += p;
            }
            const float inv = 1.0f / sm;
            for (int s = 0; s < deg; s++)
                g_csr_attn[(size_t)(beg + s) * HH + lane] *= inv;
        }
    }

    if (t == 0) g_cnt[node] = 0;
}

// ---------------------------------------------------------------------------
// agg (unchanged)
// ---------------------------------------------------------------------------
__global__ __launch_bounds__(192) void agg_kernel(
    const __half* __restrict__ hin, __half* __restrict__ hout,
    __nv_bfloat16* __restrict__ dst_split)
{
    const int node = blockIdx.x;
    const int t    = threadIdx.x;
    const int w    = t >> 5, lane = t & 31;
    const int beg  = g_rowptr[node], end = g_rowptr[node + 1];
    const int col  = w * 128 + lane * 4;
    const int hsel = lane >> 4;

    float4 acc = {0.0f, 0.0f, 0.0f, 0.0f};

    for (int cs = beg; cs < end; cs += 16) {
        const int c = min(16, end - cs);
        int   src_r  = 0;
        float attn_r = 0.0f;
        if (lane < c) src_r = g_csr_src[cs + lane];
        {
            const int e = lane >> 1;
            if (e < c)
                attn_r = g_csr_attn[(size_t)(cs + e) * HH + (w * 2 + (lane & 1))];
        }
        #pragma unroll 4
        for (int j = 0; j < c; j++) {
            const int   srcj = __shfl_sync(0xFFFFFFFFu, src_r, j);
            const float wt   = __shfl_sync(0xFFFFFFFFu, attn_r, 2 * j + hsel);
            const uint2 pv = *reinterpret_cast<const uint2*>(
                hin + (size_t)srcj * DD + col);
            const float2 h0 = __half22float2(*reinterpret_cast<const __half2*>(&pv.x));
            const float2 h1 = __half22float2(*reinterpret_cast<const __half2*>(&pv.y));
            acc.x += wt * h0.x; acc.y += wt * h0.y;
            acc.z += wt * h1.x; acc.w += wt * h1.y;
        }
    }

    const uint2 vv = *reinterpret_cast<const uint2*>(
        g_vh + (size_t)node * DD + col);
    const float2 v0 = __half22float2(*reinterpret_cast<const __half2*>(&vv.x));
    const float2 v1 = __half22float2(*reinterpret_cast<const __half2*>(&vv.y));
    float4 o;
    o.x = 0.9f * acc.x + 0.1f * v0.x;
    o.y = 0.9f * acc.y + 0.1f * v0.y;
    o.z = 0.9f * acc.z + 0.1f * v1.x;
    o.w = 0.9f * acc.w + 0.1f * v1.y;

    if (dst_split) {
        float vals[4] = {o.x, o.y, o.z, o.w};
        __align__(8) __nv_bfloat16 hi[4], lo[4];
        #pragma unroll
        for (int j = 0; j < 4; j++) {
            hi[j] = __float2bfloat16(vals[j]);
            lo[j] = __float2bfloat16(vals[j] - __bfloat162float(hi[j]));
        }
        const int mtile = node >> 7, r = node & 127;
        #pragma unroll
        for (int seg = 0; seg < 3; seg++) {
            const int kp = col + seg * DD;
            const int kc = kp >> 6, cc = kp & 63;
            const size_t base = ((size_t)mtile * NCHUNK + kc) * (size_t)TILE_BYTES;
            uint32_t off = (uint32_t)(r * 128 + cc * 2);
            uint32_t sw  = off ^ ((off >> 3) & 0x70);
            *reinterpret_cast<uint2*>(reinterpret_cast<char*>(dst_split) + base + sw) =
                *reinterpret_cast<const uint2*>(seg == 2 ? lo : hi);
        }
    } else {
        __half2* op = reinterpret_cast<__half2*>(hout + (size_t)node * DD + col);
        op[0] = __floats2half2_rn(o.x, o.y);
        op[1] = __floats2half2_rn(o.z, o.w);
    }
}

// ---------------------------------------------------------------------------
// LayerNorm (unchanged)
// ---------------------------------------------------------------------------
__global__ __launch_bounds__(256) void ln_kernel(
    const float* __restrict__ y, const float* __restrict__ gamma,
    const float* __restrict__ beta, float* __restrict__ out)
{
    const int row = blockIdx.x;
    const int t   = threadIdx.x;
    const size_t base = (size_t)row * DD;

    const float x0 = y[base + t];
    const float x1 = y[base + t + 256];
    const float x2 = y[base + t + 512];

    __shared__ float sdata[256];
    sdata[t] = x0 + x1 + x2;
    __syncthreads();
    for (int off = 128; off > 0; off >>= 1) {
        if (t < off) sdata[t] += sdata[t + off];
        __syncthreads();
    }
    const float mu = sdata[0] * (1.0f / DD);
    __syncthreads();

    const float d0 = x0 - mu, d1 = x1 - mu, d2 = x2 - mu;
    sdata[t] = d0 * d0 + d1 * d1 + d2 * d2;
    __syncthreads();
    for (int off = 128; off > 0; off >>= 1) {
        if (t < off) sdata[t] += sdata[t + off];
        __syncthreads();
    }
    const float inv = rsqrtf(sdata[0] * (1.0f / DD) + 1e-12f);

    out[base + t]       = d0 * inv * gamma[t]       + beta[t];
    out[base + t + 256] = d1 * inv * gamma[t + 256] + beta[t + 256];
    out[base + t + 512] = d2 * inv * gamma[t + 512] + beta[t + 512];
}

// ---------------------------------------------------------------------------
// launch
// ---------------------------------------------------------------------------
static float* symF(const void* sym) {
    void* p = nullptr;
    cudaGetSymbolAddress(&p, sym);
    return (float*)p;
}
static __nv_bfloat16* symB(const void* sym) {
    void* p = nullptr;
    cudaGetSymbolAddress(&p, sym);
    return (__nv_bfloat16*)p;
}
static __half* symH(const void* sym) {
    void* p = nullptr;
    cudaGetSymbolAddress(&p, sym);
    return (__half*)p;
}

extern "C" void kernel_launch(void* const* d_in, const int* in_sizes, int n_in,
                              void* d_out, int out_size) {
    const float* x    = (const float*)d_in[0];
    const float* am   = (const float*)d_in[1];
    const int*   esrc = (const int*)d_in[2];
    const int*   edst = (const int*)d_in[3];
    const float* Wq   = (const float*)d_in[4];
    const float* bq   = (const float*)d_in[5];
    const float* Wk   = (const float*)d_in[6];
    const float* bk   = (const float*)d_in[7];
    const float* Wv   = (const float*)d_in[8];
    const float* bv   = (const float*)d_in[9];
    const float* Wo   = (const float*)d_in[10];
    const float* bo   = (const float*)d_in[11];
    const float* lng  = (const float*)d_in[12];
    const float* lnb  = (const float*)d_in[13];
    float* out = (float*)d_out;

    float* q  = symF(g_q);
    float* y  = symF(g_y);

    __half* kh  = symH(g_kh);
    __half* vh  = symH(g_vh);
    __half* hha = symH(g_hha);
    __half* hhb = symH(g_hhb);

    __nv_bfloat16* ax  = symB(g_ax);
    __nv_bfloat16* ah  = symB(g_ah);
    __nv_bfloat16* wqs = symB(g_wqs);
    __nv_bfloat16* wks = symB(g_wks);
    __nv_bfloat16* wvs = symB(g_wvs);
    __nv_bfloat16* wos = symB(g_wos);

    cudaFuncSetAttribute(gemm_qkv, cudaFuncAttributeMaxDynamicSharedMemorySize,
                         GEMM_SMEMW);
    cudaFuncSetAttribute(gemm_one, cudaFuncAttributeMaxDynamicSharedMemorySize,
                         GEMM_SMEM);

    // launch order keeps the 4th launch (ncu capture slot) = gemm_qkv
    split_pack_act<<<dim3(NCHUNK, NN / 128), 256>>>(x, ax);
    split_pack_w4<<<dim3(NCHUNK, DD / 128, 4), 256>>>(Wq, Wk, Wv, Wo,
                                                      wqs, wks, wvs, wos);
    count_kernel<<<(EE + 255) / 256, 256>>>(edst);
    gemm_qkv<<<dim3(9, 64), 256, GEMM_SMEMW>>>(ax, wqs, wks, wvs,
                                               bq, bk, bv, q, kh, vh);

    // finish CSR build
    scan_kernel<<<1, 1024>>>();
    scatter_kernel<<<(EE + 255) / 256, 256>>>(esrc, edst);

    // fused CSR-order scores + per-node softmax (+ g_cnt reset)
    score_softmax<<<NN, 256>>>(am);

    // 5 message-passing steps on fp16 h; last writes bf16 split tiles
    agg_kernel<<<NN, 192>>>(vh,  hha, nullptr);
    agg_kernel<<<NN, 192>>>(hha, hhb, nullptr);
    agg_kernel<<<NN, 192>>>(hhb, hha, nullptr);
    agg_kernel<<<NN, 192>>>(hha, hhb, nullptr);
    agg_kernel<<<NN, 192>>>(hhb, nullptr, ah);

    // output projection (+x residual), then LayerNorm
    gemm_one<<<dim3(6, 64), 256, GEMM_SMEM>>>(ah, wos, bo, x, y, 1.0f);
    ln_kernel<<<NN, 256>>>(y, lng, lnb, out);
}

// round 17
// speedup vs baseline: 1.0728x; 1.0380x over previous
#include <cuda_runtime.h>
#include <cuda_bf16.h>
#include <cuda_fp16.h>
#include <cstdint>

// ---------------------------------------------------------------------------
// Problem constants
// ---------------------------------------------------------------------------
#define NN    8192          // B*S nodes
#define DD    768           // hidden dim
#define HH    12            // heads
#define HDIM  64            // head dim
#define EE    131072        // edges
#define DEGCAP 128          // smem softmax capacity

// split-bf16 GEMM constants
#define KSPLIT 2304         // 3*DD (hi|hi|lo vs hi|lo|hi)
#define NCHUNK 36           // KSPLIT/64
#define MT     128          // M tile
#define TILE_BYTES 16384    // 128 rows * 128 bytes
#define NSTAGE 4
#define GEMM_SMEM  (NSTAGE * 2 * TILE_BYTES + 128)   // 128KB + pad (narrow)
#define GEMM_SMEMW (NSTAGE * 3 * TILE_BYTES + 128)   // 192KB + pad (wide)

// ---------------------------------------------------------------------------
// Scratch (static device globals — no allocation allowed)
// ---------------------------------------------------------------------------
__device__ float g_q[NN * DD];
__device__ float g_y[NN * DD];

__device__ __half g_kh[NN * DD];
__device__ __half g_vh[NN * DD];
__device__ __half g_hha[NN * DD];
__device__ __half g_hhb[NN * DD];

__device__ int   g_cnt[NN];
__device__ int   g_rowptr[NN + 1];
__device__ int   g_csr_src[EE];
__device__ float g_csr_attn[EE * HH];

__device__ __align__(128) __nv_bfloat16 g_ax[(size_t)NN * KSPLIT];
__device__ __align__(128) __nv_bfloat16 g_ah[(size_t)NN * KSPLIT];
__device__ __align__(128) __nv_bfloat16 g_wqs[(size_t)DD * KSPLIT];
__device__ __align__(128) __nv_bfloat16 g_wks[(size_t)DD * KSPLIT];
__device__ __align__(128) __nv_bfloat16 g_wvs[(size_t)DD * KSPLIT];
__device__ __align__(128) __nv_bfloat16 g_wos[(size_t)DD * KSPLIT];

// ---------------------------------------------------------------------------
// helpers
// ---------------------------------------------------------------------------
__device__ __forceinline__ uint32_t smem_u32(const void* p) {
    uint32_t a;
    asm("{ .reg .u64 t; cvta.to.shared.u64 t, %1; cvt.u32.u64 %0, t; }"
        : "=r"(a) : "l"(p));
    return a;
}

__device__ __forceinline__ void ldmx4(uint32_t* r, uint32_t addr) {
    asm volatile("ldmatrix.sync.aligned.m8n8.x4.shared.b16 {%0,%1,%2,%3}, [%4];"
        : "=r"(r[0]), "=r"(r[1]), "=r"(r[2]), "=r"(r[3]) : "r"(addr));
}

__device__ __forceinline__ void mma_bf16(float* c, const uint32_t* a,
                                         uint32_t b0, uint32_t b1) {
    asm volatile(
        "mma.sync.aligned.m16n8k16.row.col.f32.bf16.bf16.f32 "
        "{%0,%1,%2,%3}, {%4,%5,%6,%7}, {%8,%9}, {%0,%1,%2,%3};"
        : "+f"(c[0]), "+f"(c[1]), "+f"(c[2]), "+f"(c[3])
        : "r"(a[0]), "r"(a[1]), "r"(a[2]), "r"(a[3]), "r"(b0), "r"(b1));
}

// ---------------------------------------------------------------------------
// split_pack (tile-block mapping)
// ---------------------------------------------------------------------------
__device__ __forceinline__ void split_pack_tile_body(
    const float* __restrict__ src, __nv_bfloat16* __restrict__ dst,
    int lo_seg, int kc, int mtile)
{
    const int seg   = kc / 12;
    const int kbase = kc * 64 - seg * DD;
    const bool is_lo = (seg == lo_seg);
    char* out = reinterpret_cast<char*>(dst) +
                ((size_t)mtile * NCHUNK + kc) * (size_t)TILE_BYTES;
    const float* sbase = src + (size_t)mtile * 128 * DD + kbase;

    #pragma unroll
    for (int ii = 0; ii < 4; ii++) {
        const int i  = threadIdx.x + ii * 256;
        const int r  = i >> 3;
        const int gg = i & 7;
        const float* s = sbase + (size_t)r * DD + gg * 8;
        const float4 f0 = *reinterpret_cast<const float4*>(s);
        const float4 f1 = *reinterpret_cast<const float4*>(s + 4);
        float fv[8] = {f0.x, f0.y, f0.z, f0.w, f1.x, f1.y, f1.z, f1.w};

        __align__(16) __nv_bfloat16 vals[8];
        #pragma unroll
        for (int j = 0; j < 8; j++) {
            __nv_bfloat16 hi = __float2bfloat16(fv[j]);
            vals[j] = is_lo ? __float2bfloat16(fv[j] - __bfloat162float(hi))
                            : hi;
        }
        uint32_t off = (uint32_t)(r * 128 + gg * 16);
        uint32_t sw  = off ^ ((off >> 3) & 0x70);
        *reinterpret_cast<uint4*>(out + sw) =
            *reinterpret_cast<const uint4*>(vals);
    }
}

__global__ __launch_bounds__(256) void split_pack_act(
    const float* __restrict__ src, __nv_bfloat16* __restrict__ dst)
{
    split_pack_tile_body(src, dst, 2, blockIdx.x, blockIdx.y);
}

__global__ __launch_bounds__(256) void split_pack_w4(
    const float* __restrict__ w0, const float* __restrict__ w1,
    const float* __restrict__ w2, const float* __restrict__ w3,
    __nv_bfloat16* __restrict__ d0, __nv_bfloat16* __restrict__ d1,
    __nv_bfloat16* __restrict__ d2, __nv_bfloat16* __restrict__ d3)
{
    const float* src; __nv_bfloat16* dst;
    switch (blockIdx.z) {
        case 0:  src = w0; dst = d0; break;
        case 1:  src = w1; dst = d1; break;
        case 2:  src = w2; dst = d2; break;
        default: src = w3; dst = d3; break;
    }
    split_pack_tile_body(src, dst, 1, blockIdx.x, blockIdx.y);
}

// ---------------------------------------------------------------------------
// WIDE GEMM (qkv): CTA 128x256, 8 warps 32x128 (4Mx2N), 4-stage cp.async.
// q/k use the 2-TERM split (skip chunks 12..23: act hi|lo x weight hi|hi);
// v uses the full 3-term split (all 36 chunks).
// q -> fp32; k,v -> fp16.
// ---------------------------------------------------------------------------
__global__ __launch_bounds__(256, 1)
void gemm_qkv(const __nv_bfloat16* __restrict__ Ab,
              const __nv_bfloat16* __restrict__ Wq,
              const __nv_bfloat16* __restrict__ Wk,
              const __nv_bfloat16* __restrict__ Wv,
              const float* __restrict__ bq, const float* __restrict__ bk,
              const float* __restrict__ bv,
              float* __restrict__ q, __half* __restrict__ kh,
              __half* __restrict__ vh)
{
    extern __shared__ char dyn_smem[];
    const uint32_t sbase = (smem_u32(dyn_smem) + 127u) & ~127u;

    const int sel  = blockIdx.x / 3;           // 0=q 1=k 2=v
    const int ncol = blockIdx.x % 3;           // 256-col tile
    const int mtile = blockIdx.y;
    const __nv_bfloat16* W = (sel == 0) ? Wq : (sel == 1) ? Wk : Wv;
    const float* bias      = (sel == 0) ? bq : (sel == 1) ? bk : bv;
    const float scale      = (sel == 0) ? 0.125f : 1.0f;

    // 2-term split for q/k: 24 chunks (skip 12..23); v: full 36
    const int nch = (sel == 2) ? NCHUNK : 24;

    const char* Asrc  = (const char*)Ab + (size_t)mtile * NCHUNK * TILE_BYTES;
    const char* Wsrc0 = (const char*)W  + (size_t)(2 * ncol)     * NCHUNK * TILE_BYTES;
    const char* Wsrc1 = (const char*)W  + (size_t)(2 * ncol + 1) * NCHUNK * TILE_BYTES;

    const int tid  = threadIdx.x;
    const int wid  = tid >> 5, lane = tid & 31;
    const int wm   = wid & 3, wn = wid >> 2;

    const int ra  = wm * 32 + (lane & 15);
    const int rbl = (lane & 7) + ((lane >> 4) << 3);
    const int gra = (lane >> 4);
    const int grb = ((lane >> 3) & 1);

    float acc[2][16][4];
    #pragma unroll
    for (int mt = 0; mt < 2; mt++)
        #pragma unroll
        for (int nt = 0; nt < 16; nt++)
            #pragma unroll
            for (int j = 0; j < 4; j++) acc[mt][nt][j] = 0.0f;

    // chunk index remap: logical j -> packed chunk (skip 12..23 for q/k)
    auto cmap = [&](int j) { return (sel == 2 || j < 12) ? j : j + 12; };

    auto cp_stage = [&](int j, int s) {
        const int ci = cmap(j);
        const uint32_t bA = sbase + (uint32_t)s * (3 * TILE_BYTES);
        const uint32_t bW = bA + TILE_BYTES;
        const char* ga  = Asrc  + (size_t)ci * TILE_BYTES;
        const char* gw0 = Wsrc0 + (size_t)ci * TILE_BYTES;
        const char* gw1 = Wsrc1 + (size_t)ci * TILE_BYTES;
        #pragma unroll
        for (int j2 = 0; j2 < 4; j2++) {
            const uint32_t off = (uint32_t)(tid + j2 * 256) * 16;
            asm volatile("cp.async.cg.shared.global [%0], [%1], 16;"
                :: "r"(bA + off), "l"(ga + off) : "memory");
            asm volatile("cp.async.cg.shared.global [%0], [%1], 16;"
                :: "r"(bW + off), "l"(gw0 + off) : "memory");
            asm volatile("cp.async.cg.shared.global [%0], [%1], 16;"
                :: "r"(bW + TILE_BYTES + off), "l"(gw1 + off) : "memory");
        }
        asm volatile("cp.async.commit_group;" ::: "memory");
    };

    #pragma unroll
    for (int s = 0; s < NSTAGE - 1; s++) cp_stage(s, s);

    for (int i = 0; i < nch; i++) {
        if (i <= nch - 3)
            asm volatile("cp.async.wait_group 2;" ::: "memory");
        else if (i == nch - 2)
            asm volatile("cp.async.wait_group 1;" ::: "memory");
        else
            asm volatile("cp.async.wait_group 0;" ::: "memory");
        __syncthreads();

        if (i + NSTAGE - 1 < nch)
            cp_stage(i + NSTAGE - 1, (i + NSTAGE - 1) & (NSTAGE - 1));

        const uint32_t bufA = sbase + (uint32_t)(i & (NSTAGE - 1)) * (3 * TILE_BYTES);
        const uint32_t bufW = bufA + TILE_BYTES + (uint32_t)wn * TILE_BYTES;

        #pragma unroll
        for (int ks = 0; ks < 4; ks++) {
            uint32_t a[2][4];
            #pragma unroll
            for (int mt = 0; mt < 2; mt++) {
                const int r = ra + mt * 16;
                const int g = ks * 2 + gra;
                ldmx4(a[mt], bufA + r * 128 + ((g ^ (r & 7)) << 4));
            }
            uint32_t b[8][4];
            #pragma unroll
            for (int np = 0; np < 8; np++) {
                const int r = np * 16 + rbl;
                const int g = ks * 2 + grb;
                ldmx4(b[np], bufW + r * 128 + ((g ^ (r & 7)) << 4));
            }
            #pragma unroll
            for (int mt = 0; mt < 2; mt++)
                #pragma unroll
                for (int nt = 0; nt < 16; nt++)
                    mma_bf16(acc[mt][nt], a[mt],
                             b[nt >> 1][(nt & 1) * 2],
                             b[nt >> 1][(nt & 1) * 2 + 1]);
        }
    }

    const int row0 = mtile * MT + wm * 32;
    const int col0 = ncol * 256 + wn * 128;
    #pragma unroll
    for (int mt = 0; mt < 2; mt++) {
        #pragma unroll
        for (int nt = 0; nt < 16; nt++) {
            const int r  = row0 + mt * 16 + (lane >> 2);
            const int cc = col0 + nt * 8 + (lane & 3) * 2;
            const float b0 = bias[cc], b1 = bias[cc + 1];
            float2 o0, o1;
            o0.x = (acc[mt][nt][0] + b0) * scale;
            o0.y = (acc[mt][nt][1] + b1) * scale;
            o1.x = (acc[mt][nt][2] + b0) * scale;
            o1.y = (acc[mt][nt][3] + b1) * scale;
            if (sel == 0) {
                *reinterpret_cast<float2*>(q + (size_t)r * DD + cc)       = o0;
                *reinterpret_cast<float2*>(q + (size_t)(r + 8) * DD + cc) = o1;
            } else {
                __half* Ch = (sel == 1) ? kh : vh;
                *reinterpret_cast<__half2*>(Ch + (size_t)r * DD + cc) =
                    __floats2half2_rn(o0.x, o0.y);
                *reinterpret_cast<__half2*>(Ch + (size_t)(r + 8) * DD + cc) =
                    __floats2half2_rn(o1.x, o1.y);
            }
        }
    }
}

// ---------------------------------------------------------------------------
// NARROW GEMM (output projection): CTA 128x128, full 3-term split
// ---------------------------------------------------------------------------
__global__ __launch_bounds__(256, 1)
void gemm_one(const __nv_bfloat16* __restrict__ Ab,
              const __nv_bfloat16* __restrict__ Wb,
              const float* __restrict__ bias,
              const float* __restrict__ resid,
              float* __restrict__ C, float scale)
{
    extern __shared__ char dyn_smem[];
    const uint32_t sbase = (smem_u32(dyn_smem) + 127u) & ~127u;
    const int mtile = blockIdx.y, ncol = blockIdx.x;

    const char* Asrc = (const char*)Ab + (size_t)mtile * NCHUNK * TILE_BYTES;
    const char* Wsrc = (const char*)Wb + (size_t)ncol  * NCHUNK * TILE_BYTES;

    const int tid  = threadIdx.x;
    const int wid  = tid >> 5, lane = tid & 31;
    const int wm   = wid & 3, wn = wid >> 2;

    float acc[2][8][4];
    #pragma unroll
    for (int mt = 0; mt < 2; mt++)
        #pragma unroll
        for (int nt = 0; nt < 8; nt++)
            #pragma unroll
            for (int j = 0; j < 4; j++) acc[mt][nt][j] = 0.0f;

    auto cp_stage = [&](int i, int s) {
        const uint32_t bA = sbase + (uint32_t)s * (2 * TILE_BYTES);
        const char* ga = Asrc + (size_t)i * TILE_BYTES;
        const char* gw = Wsrc + (size_t)i * TILE_BYTES;
        #pragma unroll
        for (int j = 0; j < 4; j++) {
            const uint32_t off = (uint32_t)(tid + j * 256) * 16;
            asm volatile("cp.async.cg.shared.global [%0], [%1], 16;"
                :: "r"(bA + off), "l"(ga + off) : "memory");
            asm volatile("cp.async.cg.shared.global [%0], [%1], 16;"
                :: "r"(bA + TILE_BYTES + off), "l"(gw + off) : "memory");
        }
        asm volatile("cp.async.commit_group;" ::: "memory");
    };

    #pragma unroll
    for (int s = 0; s < NSTAGE - 1; s++) cp_stage(s, s);

    for (int i = 0; i < NCHUNK; i++) {
        if (i <= NCHUNK - 3)
            asm volatile("cp.async.wait_group 2;" ::: "memory");
        else if (i == NCHUNK - 2)
            asm volatile("cp.async.wait_group 1;" ::: "memory");
        else
            asm volatile("cp.async.wait_group 0;" ::: "memory");
        __syncthreads();

        if (i + NSTAGE - 1 < NCHUNK)
            cp_stage(i + NSTAGE - 1, (i + NSTAGE - 1) & (NSTAGE - 1));

        const uint32_t bufA = sbase + (uint32_t)(i & (NSTAGE - 1)) * (2 * TILE_BYTES);
        const uint32_t bufW = bufA + TILE_BYTES;

        #pragma unroll
        for (int ks = 0; ks < 4; ks++) {
            uint32_t a[2][4];
            #pragma unroll
            for (int mt = 0; mt < 2; mt++) {
                const int r = wm * 32 + mt * 16 + (lane & 15);
                const int gr = ks * 2 + (lane >> 4);
                ldmx4(a[mt], bufA + r * 128 + ((gr ^ (r & 7)) << 4));
            }
            uint32_t b[4][4];
            #pragma unroll
            for (int np = 0; np < 4; np++) {
                const int r = wn * 64 + np * 16 + (lane & 7) + ((lane >> 4) << 3);
                const int gr = ks * 2 + ((lane >> 3) & 1);
                ldmx4(b[np], bufW + r * 128 + ((gr ^ (r & 7)) << 4));
            }
            #pragma unroll
            for (int mt = 0; mt < 2; mt++)
                #pragma unroll
                for (int nt = 0; nt < 8; nt++)
                    mma_bf16(acc[mt][nt], a[mt],
                             b[nt >> 1][(nt & 1) * 2],
                             b[nt >> 1][(nt & 1) * 2 + 1]);
        }
    }

    const int row0 = mtile * MT + wm * 32;
    const int col0 = ncol * 128 + wn * 64;
    #pragma unroll
    for (int mt = 0; mt < 2; mt++) {
        #pragma unroll
        for (int nt = 0; nt < 8; nt++) {
            const int r  = row0 + mt * 16 + (lane >> 2);
            const int cc = col0 + nt * 8 + (lane & 3) * 2;
            const float b0 = bias[cc], b1 = bias[cc + 1];
            float2 o0, o1;
            o0.x = (acc[mt][nt][0] + b0) * scale + resid[(size_t)r * DD + cc];
            o0.y = (acc[mt][nt][1] + b1) * scale + resid[(size_t)r * DD + cc + 1];
            o1.x = (acc[mt][nt][2] + b0) * scale + resid[(size_t)(r + 8) * DD + cc];
            o1.y = (acc[mt][nt][3] + b1) * scale + resid[(size_t)(r + 8) * DD + cc + 1];
            *reinterpret_cast<float2*>(C + (size_t)r * DD + cc)       = o0;
            *reinterpret_cast<float2*>(C + (size_t)(r + 8) * DD + cc) = o1;
        }
    }
}

// ---------------------------------------------------------------------------
// CSR build (g_cnt == 0 at call entry; reset by score_softmax every call)
// ---------------------------------------------------------------------------
__global__ void count_kernel(const int* __restrict__ dst) {
    int e = blockIdx.x * blockDim.x + threadIdx.x;
    if (e < EE) atomicAdd(&g_cnt[dst[e]], 1);
}

__global__ __launch_bounds__(1024) void scan_kernel() {
    __shared__ int ssum[1024];
    const int t = threadIdx.x;
    const int base = t * 8;
    int local[8];
    int s = 0;
    #pragma unroll
    for (int i = 0; i < 8; i++) { local[i] = g_cnt[base + i]; s += local[i]; }
    ssum[t] = s;
    __syncthreads();
    for (int off = 1; off < 1024; off <<= 1) {
        int v = (t >= off) ? ssum[t - off] : 0;
        __syncthreads();
        ssum[t] += v;
        __syncthreads();
    }
    int pre = (t == 0) ? 0 : ssum[t - 1];
    #pragma unroll
    for (int i = 0; i < 8; i++) {
        g_rowptr[base + i] = pre;
        pre += local[i];
        g_cnt[base + i] = 0;
    }
    if (t == 1023) g_rowptr[NN] = pre;
}

__global__ void scatter_kernel(const int* __restrict__ src,
                               const int* __restrict__ dst) {
    int e = blockIdx.x * blockDim.x + threadIdx.x;
    if (e < EE) {
        int d = dst[e];
        int pos = g_rowptr[d] + atomicAdd(&g_cnt[d], 1);
        g_csr_src[pos] = src[e];
    }
}

// ---------------------------------------------------------------------------
// score_softmax (unchanged)
// ---------------------------------------------------------------------------
__global__ __launch_bounds__(256) void score_softmax(const float* __restrict__ am) {
    __shared__ float qs[DD];
    __shared__ float sc[DEGCAP * HH];
    __shared__ float red[8 * HH];
    __shared__ float mxs[HH], invs[HH];

    const int node = blockIdx.x;
    const int t    = threadIdx.x;
    const int wid  = t >> 5, lane = t & 31;

    qs[t]       = g_q[(size_t)node * DD + t];
    qs[t + 256] = g_q[(size_t)node * DD + t + 256];
    qs[t + 512] = g_q[(size_t)node * DD + t + 512];
    const bool m = (am[node] >= 0.0f);
    __syncthreads();

    const int beg = g_rowptr[node];
    const int deg = g_rowptr[node + 1] - beg;

    for (int s = wid; s < deg; s += 8) {
        const __half* kr = g_kh + (size_t)g_csr_src[beg + s] * DD;
        float myscore = 0.0f;
        #pragma unroll
        for (int h = 0; h < HH; h++) {
            const int i0 = h * HDIM + lane * 2;
            const float2 kf = __half22float2(
                *reinterpret_cast<const __half2*>(kr + i0));
            const float2 qf = *reinterpret_cast<const float2*>(qs + i0);
            float p = kf.x * qf.x + kf.y * qf.y;
            #pragma unroll
            for (int off = 16; off; off >>= 1)
                p += __shfl_xor_sync(0xFFFFFFFFu, p, off);
            if (lane == h) myscore = m ? p : -1.0e4f;
        }
        if (lane < HH) {
            if (s < DEGCAP) sc[s * HH + lane] = myscore;
            else g_csr_attn[(size_t)(beg + s) * HH + lane] = myscore;
        }
    }
    __syncthreads();

    if (deg <= DEGCAP) {
        if (t < 8 * HH) {
            const int h = t % HH, g = t / HH;
            float mx = -3.0e38f;
            for (int s = g; s < deg; s += 8) mx = fmaxf(mx, sc[s * HH + h]);
            red[g * HH + h] = mx;
        }
        __syncthreads();
        if (t < HH) {
            float mx = red[t];
            #pragma unroll
            for (int g = 1; g < 8; g++) mx = fmaxf(mx, red[g * HH + t]);
            mxs[t] = mx;
        }
        __syncthreads();
        if (t < 8 * HH) {
            const int h = t % HH, g = t / HH;
            const float mx = mxs[h];
            float sm = 0.0f;
            for (int s = g; s < deg; s += 8) {
                float p = __expf(sc[s * HH + h] - mx);
                sc[s * HH + h] = p;
                sm += p;
            }
            red[g * HH + h] = sm;
        }
        __syncthreads();
        if (t < HH) {
            float sm = 0.0f;
            #pragma unroll
            for (int g = 0; g < 8; g++) sm += red[g * HH + t];
            invs[t] = 1.0f / sm;
        }
        __syncthreads();
        for (int i = t; i < deg * HH; i += 256)
            g_csr_attn[(size_t)beg * HH + i] = sc[i] * invs[i % HH];
    } else {
        for (int i = t; i < DEGCAP * HH; i += 256)
            g_csr_attn[(size_t)beg * HH + i] = sc[i];
        __syncthreads();
        if (wid == 0 && lane < HH) {
            float mx = -3.0e38f;
            for (int s = 0; s < deg; s++)
                mx = fmaxf(mx, g_csr_attn[(size_t)(beg + s) * HH + lane]);
            float sm = 0.0f;
            for (int s = 0; s < deg; s++) {
                float p = __expf(g_csr_attn[(size_t)(beg + s) * HH + lane] - mx);
                g_csr_attn[(size_t)(beg + s) * HH + lane] = p;
                sm += p;
            }
            const float inv = 1.0f / sm;
            for (int s = 0; s < deg; s++)
                g_csr_attn[(size_t)(beg + s) * HH + lane] *= inv;
        }
    }

    if (t == 0) g_cnt[node] = 0;
}

// ---------------------------------------------------------------------------
// agg (unchanged)
// ---------------------------------------------------------------------------
__global__ __launch_bounds__(192) void agg_kernel(
    const __half* __restrict__ hin, __half* __restrict__ hout,
    __nv_bfloat16* __restrict__ dst_split)
{
    const int node = blockIdx.x;
    const int t    = threadIdx.x;
    const int w    = t >> 5, lane = t & 31;
    const int beg  = g_rowptr[node], end = g_rowptr[node + 1];
    const int col  = w * 128 + lane * 4;
    const int hsel = lane >> 4;

    float4 acc = {0.0f, 0.0f, 0.0f, 0.0f};

    for (int cs = beg; cs < end; cs += 16) {
        const int c = min(16, end - cs);
        int   src_r  = 0;
        float attn_r = 0.0f;
        if (lane < c) src_r = g_csr_src[cs + lane];
        {
            const int e = lane >> 1;
            if (e < c)
                attn_r = g_csr_attn[(size_t)(cs + e) * HH + (w * 2 + (lane & 1))];
        }
        #pragma unroll 4
        for (int j = 0; j < c; j++) {
            const int   srcj = __shfl_sync(0xFFFFFFFFu, src_r, j);
            const float wt   = __shfl_sync(0xFFFFFFFFu, attn_r, 2 * j + hsel);
            const uint2 pv = *reinterpret_cast<const uint2*>(
                hin + (size_t)srcj * DD + col);
            const float2 h0 = __half22float2(*reinterpret_cast<const __half2*>(&pv.x));
            const float2 h1 = __half22float2(*reinterpret_cast<const __half2*>(&pv.y));
            acc.x += wt * h0.x; acc.y += wt * h0.y;
            acc.z += wt * h1.x; acc.w += wt * h1.y;
        }
    }

    const uint2 vv = *reinterpret_cast<const uint2*>(
        g_vh + (size_t)node * DD + col);
    const float2 v0 = __half22float2(*reinterpret_cast<const __half2*>(&vv.x));
    const float2 v1 = __half22float2(*reinterpret_cast<const __half2*>(&vv.y));
    float4 o;
    o.x = 0.9f * acc.x + 0.1f * v0.x;
    o.y = 0.9f * acc.y + 0.1f * v0.y;
    o.z = 0.9f * acc.z + 0.1f * v1.x;
    o.w = 0.9f * acc.w + 0.1f * v1.y;

    if (dst_split) {
        float vals[4] = {o.x, o.y, o.z, o.w};
        __align__(8) __nv_bfloat16 hi[4], lo[4];
        #pragma unroll
        for (int j = 0; j < 4; j++) {
            hi[j] = __float2bfloat16(vals[j]);
            lo[j] = __float2bfloat16(vals[j] - __bfloat162float(hi[j]));
        }
        const int mtile = node >> 7, r = node & 127;
        #pragma unroll
        for (int seg = 0; seg < 3; seg++) {
            const int kp = col + seg * DD;
            const int kc = kp >> 6, cc = kp & 63;
            const size_t base = ((size_t)mtile * NCHUNK + kc) * (size_t)TILE_BYTES;
            uint32_t off = (uint32_t)(r * 128 + cc * 2);
            uint32_t sw  = off ^ ((off >> 3) & 0x70);
            *reinterpret_cast<uint2*>(reinterpret_cast<char*>(dst_split) + base + sw) =
                *reinterpret_cast<const uint2*>(seg == 2 ? lo : hi);
        }
    } else {
        __half2* op = reinterpret_cast<__half2*>(hout + (size_t)node * DD + col);
        op[0] = __floats2half2_rn(o.x, o.y);
        op[1] = __floats2half2_rn(o.z, o.w);
    }
}

// ---------------------------------------------------------------------------
// LayerNorm (unchanged)
// ---------------------------------------------------------------------------
__global__ __launch_bounds__(256) void ln_kernel(
    const float* __restrict__ y, const float* __restrict__ gamma,
    const float* __restrict__ beta, float* __restrict__ out)
{
    const int row = blockIdx.x;
    const int t   = threadIdx.x;
    const size_t base = (size_t)row * DD;

    const float x0 = y[base + t];
    const float x1 = y[base + t + 256];
    const float x2 = y[base + t + 512];

    __shared__ float sdata[256];
    sdata[t] = x0 + x1 + x2;
    __syncthreads();
    for (int off = 128; off > 0; off >>= 1) {
        if (t < off) sdata[t] += sdata[t + off];
        __syncthreads();
    }
    const float mu = sdata[0] * (1.0f / DD);
    __syncthreads();

    const float d0 = x0 - mu, d1 = x1 - mu, d2 = x2 - mu;
    sdata[t] = d0 * d0 + d1 * d1 + d2 * d2;
    __syncthreads();
    for (int off = 128; off > 0; off >>= 1) {
        if (t < off) sdata[t] += sdata[t + off];
        __syncthreads();
    }
    const float inv = rsqrtf(sdata[0] * (1.0f / DD) + 1e-12f);

    out[base + t]       = d0 * inv * gamma[t]       + beta[t];
    out[base + t + 256] = d1 * inv * gamma[t + 256] + beta[t + 256];
    out[base + t + 512] = d2 * inv * gamma[t + 512] + beta[t + 512];
}

// ---------------------------------------------------------------------------
// launch
// ---------------------------------------------------------------------------
static float* symF(const void* sym) {
    void* p = nullptr;
    cudaGetSymbolAddress(&p, sym);
    return (float*)p;
}
static __nv_bfloat16* symB(const void* sym) {
    void* p = nullptr;
    cudaGetSymbolAddress(&p, sym);
    return (__nv_bfloat16*)p;
}
static __half* symH(const void* sym) {
    void* p = nullptr;
    cudaGetSymbolAddress(&p, sym);
    return (__half*)p;
}

extern "C" void kernel_launch(void* const* d_in, const int* in_sizes, int n_in,
                              void* d_out, int out_size) {
    const float* x    = (const float*)d_in[0];
    const float* am   = (const float*)d_in[1];
    const int*   esrc = (const int*)d_in[2];
    const int*   edst = (const int*)d_in[3];
    const float* Wq   = (const float*)d_in[4];
    const float* bq   = (const float*)d_in[5];
    const float* Wk   = (const float*)d_in[6];
    const float* bk   = (const float*)d_in[7];
    const float* Wv   = (const float*)d_in[8];
    const float* bv   = (const float*)d_in[9];
    const float* Wo   = (const float*)d_in[10];
    const float* bo   = (const float*)d_in[11];
    const float* lng  = (const float*)d_in[12];
    const float* lnb  = (const float*)d_in[13];
    float* out = (float*)d_out;

    float* q  = symF(g_q);
    float* y  = symF(g_y);

    __half* kh  = symH(g_kh);
    __half* vh  = symH(g_vh);
    __half* hha = symH(g_hha);
    __half* hhb = symH(g_hhb);

    __nv_bfloat16* ax  = symB(g_ax);
    __nv_bfloat16* ah  = symB(g_ah);
    __nv_bfloat16* wqs = symB(g_wqs);
    __nv_bfloat16* wks = symB(g_wks);
    __nv_bfloat16* wvs = symB(g_wvs);
    __nv_bfloat16* wos = symB(g_wos);

    cudaFuncSetAttribute(gemm_qkv, cudaFuncAttributeMaxDynamicSharedMemorySize,
                         GEMM_SMEMW);
    cudaFuncSetAttribute(gemm_one, cudaFuncAttributeMaxDynamicSharedMemorySize,
                         GEMM_SMEM);

    // launch order keeps the 4th launch (ncu capture slot) = gemm_qkv
    split_pack_act<<<dim3(NCHUNK, NN / 128), 256>>>(x, ax);
    split_pack_w4<<<dim3(NCHUNK, DD / 128, 4), 256>>>(Wq, Wk, Wv, Wo,
                                                      wqs, wks, wvs, wos);
    count_kernel<<<(EE + 255) / 256, 256>>>(edst);
    gemm_qkv<<<dim3(9, 64), 256, GEMM_SMEMW>>>(ax, wqs, wks, wvs,
                                               bq, bk, bv, q, kh, vh);

    // finish CSR build
    scan_kernel<<<1, 1024>>>();
    scatter_kernel<<<(EE + 255) / 256, 256>>>(esrc, edst);

    // fused CSR-order scores + per-node softmax (+ g_cnt reset)
    score_softmax<<<NN, 256>>>(am);

    // 5 message-passing steps on fp16 h; last writes bf16 split tiles
    agg_kernel<<<NN, 192>>>(vh,  hha, nullptr);
    agg_kernel<<<NN, 192>>>(hha, hhb, nullptr);
    agg_kernel<<<NN, 192>>>(hhb, hha, nullptr);
    agg_kernel<<<NN, 192>>>(hha, hhb, nullptr);
    agg_kernel<<<NN, 192>>>(hhb, nullptr, ah);

    // output projection (+x residual), then LayerNorm
    gemm_one<<<dim3(6, 64), 256, GEMM_SMEM>>>(ah, wos, bo, x, y, 1.0f);
    ln_kernel<<<NN, 256>>>(y, lng, lnb, out);
}